// round 8
// baseline (speedup 1.0000x reference)
#include <cuda_runtime.h>
#include <cuda_fp16.h>
#include <cstdint>

#define MROWS 8192
#define NCOLS 8192
#define DIN   128
#define DH    256
#define TOPK  512

// ---------- MLP tiling ----------
#define BM 128
#define BN 128
#define BK 16
#define NTHREADS 256

// ---------- sim tiling (fp16 m16n8k16, 3-term split, term-inner) ----------
#define TM 128
#define TN 256
#define KCH 16               // k per stage
#define NST 16               // 256 / 16 stages
#define NBUF 4
#define SH 24                // halves per smem row (16 data + 8 pad)
#define AH_OFF 0
#define AL_OFF (128 * SH)
#define BH_OFF (256 * SH)
#define BL_OFF (512 * SH)
#define STG (768 * SH)       // halves per stage buffer (18432)
#define SIM_SMEM (NBUF * STG * 2)   // 147456 B

#define NBX (NCOLS / TN)     // 32
#define NBY (MROWS / TM)     // 64
#define NBLOCKS (NBX * NBY)  // 2048

#define CAND_BUF  32768
#define CAND_SORT 4096

// ---------------- scratch (device globals; no allocation allowed) ----------
__device__ __align__(128) float g_hid0[MROWS * DH];
__device__ __align__(128) float g_hid1[NCOLS * DH];
__device__ __align__(128) float g_md0[MROWS * DH];    // exact fp32 (recompute)
__device__ __align__(128) float g_md1[NCOLS * DH];
__device__ __align__(128) __half g_ah[MROWS * DH];    // fp16 hi
__device__ __align__(128) __half g_al[MROWS * DH];    // fp16 lo
__device__ __align__(128) __half g_bh[NCOLS * DH];
__device__ __align__(128) __half g_bl[NCOLS * DH];
__device__ float g_blockmax[NBLOCKS];
__device__ float g_thresh;
__device__ unsigned int g_ccount;
__device__ unsigned long long g_cand[CAND_BUF];

// monotone float -> uint key
__device__ __forceinline__ unsigned int fkey(float f) {
    unsigned int u = __float_as_uint(f);
    return (u & 0x80000000u) ? ~u : (u | 0x80000000u);
}

__device__ __forceinline__ void cp16(uint32_t smem_dst, const void* src) {
    asm volatile("cp.async.cg.shared.global [%0], [%1], 16;"
                 :: "r"(smem_dst), "l"(src) : "memory");
}

// ---------------- MLP GEMM: O = act(A @ W + b), N = DH = 256 ---------------
__global__ __launch_bounds__(NTHREADS, 2)
void mlp_gemm_kernel(const float* __restrict__ in0, const float* __restrict__ in1,
                     const float* __restrict__ Wd0, const float* __restrict__ Wd1,
                     const float* __restrict__ bd0, const float* __restrict__ bd1,
                     int layer)
{
    const int z = blockIdx.z;
    const float* A;
    int K, relu;
    float* Omd;
    __half *Oh, *Ol;
    if (layer == 0) {
        A = z ? in1 : in0;
        Omd = z ? g_hid1 : g_hid0;
        Oh = 0; Ol = 0;
        K = DIN; relu = 1;
    } else {
        A = z ? g_hid1 : g_hid0;
        Omd = z ? g_md1 : g_md0;
        Oh = z ? g_bh : g_ah;
        Ol = z ? g_bl : g_al;
        K = DH; relu = 0;
    }
    const float* W = z ? Wd1 : Wd0;
    const float* bias = z ? bd1 : bd0;

    __shared__ float As[BK][BM];
    __shared__ float Bs[BK][BN];

    const int tid = threadIdx.x;
    const int tx = tid & 15, ty = tid >> 4;
    const int r0 = blockIdx.y * BM;
    const int c0 = blockIdx.x * BN;

    float acc[8][8];
#pragma unroll
    for (int i = 0; i < 8; i++)
#pragma unroll
        for (int j = 0; j < 8; j++) acc[i][j] = 0.0f;

    for (int k0 = 0; k0 < K; k0 += BK) {
#pragma unroll
        for (int i = 0; i < 2; i++) {
            int f = tid * 2 + i;
            int row = f >> 2;
            int kq = (f & 3) << 2;
            float4 v = *(const float4*)(A + (size_t)(r0 + row) * K + k0 + kq);
            As[kq + 0][row] = v.x; As[kq + 1][row] = v.y;
            As[kq + 2][row] = v.z; As[kq + 3][row] = v.w;
        }
#pragma unroll
        for (int i = 0; i < 2; i++) {
            int f = tid * 2 + i;
            int kk = f >> 5;
            int nq = (f & 31) << 2;
            *(float4*)&Bs[kk][nq] =
                *(const float4*)(W + (size_t)(k0 + kk) * DH + c0 + nq);
        }
        __syncthreads();
#pragma unroll
        for (int kk = 0; kk < BK; kk++) {
            float a[8], b[8];
            *(float4*)&a[0] = *(float4*)&As[kk][ty * 8];
            *(float4*)&a[4] = *(float4*)&As[kk][ty * 8 + 4];
            *(float4*)&b[0] = *(float4*)&Bs[kk][tx * 8];
            *(float4*)&b[4] = *(float4*)&Bs[kk][tx * 8 + 4];
#pragma unroll
            for (int i = 0; i < 8; i++)
#pragma unroll
                for (int j = 0; j < 8; j++)
                    acc[i][j] = fmaf(a[i], b[j], acc[i][j]);
        }
        __syncthreads();
    }

    float bv[8];
    *(float4*)&bv[0] = *(const float4*)(bias + c0 + tx * 8);
    *(float4*)&bv[4] = *(const float4*)(bias + c0 + tx * 8 + 4);

#pragma unroll
    for (int i = 0; i < 8; i++) {
        int row = r0 + ty * 8 + i;
        float f[8];
#pragma unroll
        for (int j = 0; j < 8; j++) f[j] = acc[i][j] + bv[j];
        if (relu) {
#pragma unroll
            for (int j = 0; j < 8; j++) f[j] = fmaxf(f[j], 0.0f);
            *(float4*)(Omd + (size_t)row * DH + c0 + tx * 8) = *(float4*)&f[0];
            *(float4*)(Omd + (size_t)row * DH + c0 + tx * 8 + 4) = *(float4*)&f[4];
        } else {
            __half hh[8], ll[8];
#pragma unroll
            for (int j = 0; j < 8; j++) {
                __half h = __float2half_rn(f[j]);
                hh[j] = h;
                ll[j] = __float2half_rn(f[j] - __half2float(h));
            }
            size_t off = (size_t)row * DH + c0 + tx * 8;
            *(float4*)(Omd + off)     = *(float4*)&f[0];
            *(float4*)(Omd + off + 4) = *(float4*)&f[4];
            *(uint4*)(Oh + off) = *(uint4*)hh;
            *(uint4*)(Ol + off) = *(uint4*)ll;
        }
    }
}

// ---------------- no-op (aligns ncu -s 5 capture onto sim kernel) ----------
__global__ void noop_kernel() {}

// ---------------- sim GEMM: fp16 m16n8k16, term-inner 3-way split ----------
__global__ __launch_bounds__(256, 1)
void sim_mma_kernel(float* __restrict__ C)
{
    extern __shared__ __align__(128) __half hsm[];
    __shared__ float wmax[8];

    const int tid = threadIdx.x;
    const int lid = tid & 31, wid = tid >> 5;
    const int warp_m = wid >> 2, warp_n = wid & 3;   // 2 x 4 warps, 64x64 each
    const int gr = lid >> 2, gc = lid & 3;
    const int m0 = blockIdx.y * TM;
    const int n0 = blockIdx.x * TN;

    const uint32_t sbase = (uint32_t)__cvta_generic_to_shared(hsm);

    // per-thread load slots:
    //   A: tid<128 -> Ah row tid ; tid>=128 -> Al row tid-128   (2x16B)
    //   B: all     -> Bh row tid, Bl row tid                    (4x16B)
    const int arow = tid & 127;
    const __half* gA = (tid < 128 ? g_ah : g_al) + (size_t)(m0 + arow) * DH;
    const __half* gBh = g_bh + (size_t)(n0 + tid) * DH;
    const __half* gBl = g_bl + (size_t)(n0 + tid) * DH;
    const uint32_t aoff = ((tid < 128 ? AH_OFF : AL_OFF) + arow * SH) * 2;
    const uint32_t bhoff = (BH_OFF + tid * SH) * 2;
    const uint32_t bloff = (BL_OFF + tid * SH) * 2;

    float acc[4][8][4];
#pragma unroll
    for (int i = 0; i < 4; i++)
#pragma unroll
        for (int j = 0; j < 8; j++)
#pragma unroll
            for (int q = 0; q < 4; q++) acc[i][j][q] = 0.0f;

#define ISSUE(s)                                                               \
    do {                                                                       \
        const int k_ = (s) * KCH;                                              \
        const uint32_t bb_ = sbase + ((s) & (NBUF - 1)) * STG * 2;             \
        cp16(bb_ + aoff,       gA + k_);                                       \
        cp16(bb_ + aoff + 16,  gA + k_ + 8);                                   \
        cp16(bb_ + bhoff,      gBh + k_);                                      \
        cp16(bb_ + bhoff + 16, gBh + k_ + 8);                                  \
        cp16(bb_ + bloff,      gBl + k_);                                      \
        cp16(bb_ + bloff + 16, gBl + k_ + 8);                                  \
        asm volatile("cp.async.commit_group;" ::: "memory");                   \
    } while (0)

    ISSUE(0); ISSUE(1); ISSUE(2);

#pragma unroll 1
    for (int s = 0; s < NST; s++) {
        if (s <= NST - 3)
            asm volatile("cp.async.wait_group 2;" ::: "memory");
        else if (s == NST - 2)
            asm volatile("cp.async.wait_group 1;" ::: "memory");
        else
            asm volatile("cp.async.wait_group 0;" ::: "memory");
        __syncthreads();
        if (s + 3 < NST) ISSUE(s + 3);

        const __half* buf = hsm + (s & (NBUF - 1)) * STG;
#pragma unroll
        for (int t = 0; t < 3; t++) {
            const __half* Ab = buf + (t == 2 ? AL_OFF : AH_OFF);
            const __half* Bb = buf + (t == 1 ? BL_OFF : BH_OFF);
            uint32_t a[4][4], b[8][2];
#pragma unroll
            for (int i = 0; i < 4; i++) {
                const __half* p = Ab + (warp_m * 64 + i * 16 + gr) * SH + 2 * gc;
                a[i][0] = *(const uint32_t*)(p);
                a[i][1] = *(const uint32_t*)(p + 8 * SH);
                a[i][2] = *(const uint32_t*)(p + 8);
                a[i][3] = *(const uint32_t*)(p + 8 * SH + 8);
            }
#pragma unroll
            for (int j = 0; j < 8; j++) {
                const __half* p = Bb + (warp_n * 64 + j * 8 + gr) * SH + 2 * gc;
                b[j][0] = *(const uint32_t*)(p);
                b[j][1] = *(const uint32_t*)(p + 8);
            }
#pragma unroll
            for (int i = 0; i < 4; i++)
#pragma unroll
                for (int j = 0; j < 8; j++) {
                    asm volatile(
                        "mma.sync.aligned.m16n8k16.row.col.f32.f16.f16.f32 "
                        "{%0,%1,%2,%3}, {%4,%5,%6,%7}, {%8,%9}, {%0,%1,%2,%3};"
                        : "+f"(acc[i][j][0]), "+f"(acc[i][j][1]),
                          "+f"(acc[i][j][2]), "+f"(acc[i][j][3])
                        : "r"(a[i][0]), "r"(a[i][1]), "r"(a[i][2]), "r"(a[i][3]),
                          "r"(b[j][0]), "r"(b[j][1]));
                }
        }
        __syncthreads();
    }
#undef ISSUE

    // ---- epilogue: streaming stores + block max ----
    float bmax = -3.0e38f;
#pragma unroll
    for (int i = 0; i < 4; i++) {
#pragma unroll
        for (int j = 0; j < 8; j++) {
            int row = m0 + warp_m * 64 + i * 16 + gr;
            int col = n0 + warp_n * 64 + j * 8 + gc * 2;
            float* d0 = C + (size_t)row * NCOLS + col;
            float* d1 = d0 + 8 * (size_t)NCOLS;
            asm volatile("st.global.cs.v2.f32 [%0], {%1,%2};"
                         :: "l"(d0), "f"(acc[i][j][0]), "f"(acc[i][j][1]) : "memory");
            asm volatile("st.global.cs.v2.f32 [%0], {%1,%2};"
                         :: "l"(d1), "f"(acc[i][j][2]), "f"(acc[i][j][3]) : "memory");
            bmax = fmaxf(bmax, fmaxf(fmaxf(acc[i][j][0], acc[i][j][1]),
                                     fmaxf(acc[i][j][2], acc[i][j][3])));
        }
    }
#pragma unroll
    for (int o = 16; o; o >>= 1) bmax = fmaxf(bmax, __shfl_xor_sync(~0u, bmax, o));
    if (lid == 0) wmax[wid] = bmax;
    __syncthreads();
    if (tid == 0) {
        float mm = wmax[0];
#pragma unroll
        for (int i = 1; i < 8; i++) mm = fmaxf(mm, wmax[i]);
        g_blockmax[blockIdx.y * gridDim.x + blockIdx.x] = mm;
    }
}

// ---------------- threshold: radix-select over 2048 block maxima -----------
__global__ void thresh_kernel()
{
    __shared__ unsigned int cs[32];
    __shared__ unsigned int Ts;
    const int tid = threadIdx.x;  // 1024 threads
    const int w = tid >> 5, l = tid & 31;
    unsigned int k0 = fkey(g_blockmax[tid]);
    unsigned int k1 = fkey(g_blockmax[tid + 1024]);
    if (tid == 0) Ts = 0u;
    __syncthreads();
    for (int bit = 31; bit >= 8; bit--) {
        unsigned int Tc = Ts | (1u << bit);
        unsigned int c = (unsigned)(k0 >= Tc) + (unsigned)(k1 >= Tc);
#pragma unroll
        for (int o = 16; o; o >>= 1) c += __shfl_xor_sync(~0u, c, o);
        if (l == 0) cs[w] = c;
        __syncthreads();
        if (tid < 32) {
            unsigned int t = cs[tid];
#pragma unroll
            for (int o = 16; o; o >>= 1) t += __shfl_xor_sync(~0u, t, o);
            if (tid == 0 && t >= TOPK) Ts = Tc;
        }
        __syncthreads();
    }
    if (tid == 0) {
        unsigned int T = Ts;
        float f;
        if (T < 0x01000000u) f = -3.0e38f;
        else if (T & 0x80000000u) f = __uint_as_float(T ^ 0x80000000u);
        else f = __uint_as_float(~T);
        g_thresh = f - (fabsf(f) * 1e-4f + 1e-6f);   // fp16-split ordering margin
        g_ccount = 0;
    }
}

// ---------------- collect candidates >= threshold ---------------------------
__device__ __forceinline__ void push_cand(float v, unsigned int idx)
{
    unsigned int pos = atomicAdd(&g_ccount, 1u);
    if (pos < CAND_BUF) {
        unsigned long long e =
            ((unsigned long long)fkey(v) << 32) | (unsigned int)(~idx);
        g_cand[pos] = e;
    }
}

__global__ void collect_kernel(const float* __restrict__ S)
{
    const float T = g_thresh;
    const size_t total4 = (size_t)MROWS * NCOLS / 4;
    const size_t stride = (size_t)gridDim.x * blockDim.x;
    for (size_t q = (size_t)blockIdx.x * blockDim.x + threadIdx.x;
         q < total4; q += stride) {
        float4 v = ((const float4*)S)[q];
        unsigned int base = (unsigned int)(q * 4);
        if (v.x >= T) push_cand(v.x, base + 0);
        if (v.y >= T) push_cand(v.y, base + 1);
        if (v.z >= T) push_cand(v.z, base + 2);
        if (v.w >= T) push_cand(v.w, base + 3);
    }
}

// ---------------- recompute candidate values exactly (fp64, warp/cand) -----
__global__ void recompute_kernel()
{
    unsigned int cnt = g_ccount;
    if (cnt > CAND_BUF) cnt = CAND_BUF;
    const int gw = (blockIdx.x * blockDim.x + threadIdx.x) >> 5;
    const int nw = (gridDim.x * blockDim.x) >> 5;
    const int lid = threadIdx.x & 31;
    for (unsigned int i = gw; i < cnt; i += nw) {
        unsigned long long e = g_cand[i];
        unsigned int idx = ~(unsigned int)(e & 0xFFFFFFFFull);
        int r = idx >> 13, c = idx & (NCOLS - 1);
        const float* ar = g_md0 + (size_t)r * DH;
        const float* br = g_md1 + (size_t)c * DH;
        double s = 0.0;
#pragma unroll
        for (int k = 0; k < 8; k++) {
            int kk = lid + k * 32;
            s = fma((double)ar[kk], (double)br[kk], s);
        }
#pragma unroll
        for (int o = 16; o; o >>= 1) s += __shfl_down_sync(0xffffffffu, s, o);
        if (lid == 0) {
            float v = (float)s;
            g_cand[i] = ((unsigned long long)fkey(v) << 32)
                      | (unsigned long long)(e & 0xFFFFFFFFull);
        }
    }
}

// ---------------- final: sort candidates, emit (row, col) pairs ------------
__global__ void final_kernel(float* __restrict__ out)
{
    __shared__ unsigned long long s[CAND_SORT];
    __shared__ unsigned long long red[32];
    const int tid = threadIdx.x;  // 1024 threads
    unsigned int cnt = g_ccount;
    if (cnt > CAND_BUF) cnt = CAND_BUF;

    if (cnt <= CAND_SORT) {
        for (int i = tid; i < CAND_SORT; i += 1024)
            s[i] = (i < (int)cnt) ? g_cand[i] : 0ull;
        __syncthreads();
        for (int k = 2; k <= CAND_SORT; k <<= 1) {
            for (int j = k >> 1; j > 0; j >>= 1) {
                for (int i = tid; i < CAND_SORT; i += 1024) {
                    int ixj = i ^ j;
                    if (ixj > i) {
                        bool desc = ((i & k) == 0);
                        unsigned long long a = s[i], b = s[ixj];
                        if (desc ? (a < b) : (a > b)) { s[i] = b; s[ixj] = a; }
                    }
                }
                __syncthreads();
            }
        }
        for (int i = tid; i < TOPK; i += 1024) {
            unsigned int idx = ~(unsigned int)(s[i] & 0xFFFFFFFFull);
            out[2 * i + 0] = (float)(idx >> 13);
            out[2 * i + 1] = (float)(idx & (NCOLS - 1));
        }
    } else {
        for (int r = 0; r < TOPK; r++) {
            unsigned long long best = 0ull;
            for (unsigned int i = tid; i < cnt; i += 1024) {
                unsigned long long v = g_cand[i];
                if (v > best) best = v;
            }
#pragma unroll
            for (int o = 16; o; o >>= 1) {
                unsigned long long other = __shfl_down_sync(0xffffffffu, best, o);
                if (other > best) best = other;
            }
            if ((tid & 31) == 0) red[tid >> 5] = best;
            __syncthreads();
            if (tid < 32) {
                unsigned long long b = red[tid];
#pragma unroll
                for (int o = 16; o; o >>= 1) {
                    unsigned long long other = __shfl_down_sync(0xffffffffu, b, o);
                    if (other > b) b = other;
                }
                if (tid == 0) red[0] = b;
            }
            __syncthreads();
            best = red[0];
            for (unsigned int i = tid; i < cnt; i += 1024)
                if (g_cand[i] == best) g_cand[i] = 0ull;
            if (tid == 0) {
                unsigned int idx = ~(unsigned int)(best & 0xFFFFFFFFull);
                out[2 * r + 0] = (float)(idx >> 13);
                out[2 * r + 1] = (float)(idx & (NCOLS - 1));
            }
            __syncthreads();
        }
    }
}

// ---------------- launch ----------------------------------------------------
extern "C" void kernel_launch(void* const* d_in, const int* in_sizes, int n_in,
                              void* d_out, int out_size)
{
    const float* desc0 = (const float*)d_in[0];
    const float* desc1 = (const float*)d_in[1];
    const float* W0a = (const float*)d_in[2];
    const float* b0a = (const float*)d_in[3];
    const float* W0b = (const float*)d_in[4];
    const float* b0b = (const float*)d_in[5];
    const float* W1a = (const float*)d_in[6];
    const float* b1a = (const float*)d_in[7];
    const float* W1b = (const float*)d_in[8];
    const float* b1b = (const float*)d_in[9];

    float* out = (float*)d_out;
    float* sim = out + 2 * TOPK;  // indices first, then sim [8192, 8192]

    cudaFuncSetAttribute(sim_mma_kernel,
                         cudaFuncAttributeMaxDynamicSharedMemorySize, SIM_SMEM);

    dim3 mgrid(DH / BN, MROWS / BM, 2);   // (2, 64, 2)
    mlp_gemm_kernel<<<mgrid, NTHREADS>>>(desc0, desc1, W0a, W1a, b0a, b1a, 0);
    mlp_gemm_kernel<<<mgrid, NTHREADS>>>(desc0, desc1, W0b, W1b, b0b, b1b, 1);

    noop_kernel<<<1, 32>>>();             // ncu -s 5 alignment: sim is launch #4

    dim3 sgrid(NBX, NBY);                 // (32, 64)
    sim_mma_kernel<<<sgrid, 256, SIM_SMEM>>>(sim);

    thresh_kernel<<<1, 1024>>>();
    collect_kernel<<<2048, 256>>>(sim);
    recompute_kernel<<<256, 256>>>();
    final_kernel<<<1, 1024>>>(out);
}

// round 10
// speedup vs baseline: 1.0086x; 1.0086x over previous
#include <cuda_runtime.h>
#include <cuda_fp16.h>
#include <cstdint>

#define MROWS 8192
#define NCOLS 8192
#define DIN   128
#define DH    256
#define TOPK  512

// ---------- MLP tiling ----------
#define BM 128
#define BN 128
#define BK 16
#define NTHREADS 256

// ---------- sim tiling (fp16 m16n8k16, 3-term split, ldmatrix feed) ----------
#define TM 128
#define TN 256
#define KCH 16               // k per stage
#define NST 16               // 256 / 16 stages
#define NBUF 4
#define SH 24                // halves per smem row (16 data + 8 pad)
#define AH_OFF 0
#define AL_OFF (128 * SH)
#define BH_OFF (256 * SH)
#define BL_OFF (512 * SH)
#define STG (768 * SH)       // halves per stage buffer (18432)
#define SIM_SMEM (NBUF * STG * 2)   // 147456 B

#define NBX (NCOLS / TN)     // 32
#define NBY (MROWS / TM)     // 64
#define NBLOCKS (NBX * NBY)  // 2048

#define CAND_BUF  32768
#define CAND_SORT 4096

// ---------------- scratch (device globals; no allocation allowed) ----------
__device__ __align__(128) float g_hid0[MROWS * DH];
__device__ __align__(128) float g_hid1[NCOLS * DH];
__device__ __align__(128) float g_md0[MROWS * DH];    // exact fp32 (recompute)
__device__ __align__(128) float g_md1[NCOLS * DH];
__device__ __align__(128) __half g_ah[MROWS * DH];    // fp16 hi
__device__ __align__(128) __half g_al[MROWS * DH];    // fp16 lo
__device__ __align__(128) __half g_bh[NCOLS * DH];
__device__ __align__(128) __half g_bl[NCOLS * DH];
__device__ float g_blockmax[NBLOCKS];
__device__ float g_thresh;
__device__ unsigned int g_ccount;
__device__ unsigned long long g_cand[CAND_BUF];

// monotone float -> uint key
__device__ __forceinline__ unsigned int fkey(float f) {
    unsigned int u = __float_as_uint(f);
    return (u & 0x80000000u) ? ~u : (u | 0x80000000u);
}

__device__ __forceinline__ void cp16(uint32_t smem_dst, const void* src) {
    asm volatile("cp.async.cg.shared.global [%0], [%1], 16;"
                 :: "r"(smem_dst), "l"(src) : "memory");
}

#define LDSM4(r, addr)                                                        \
    asm volatile("ldmatrix.sync.aligned.m8n8.x4.shared.b16 {%0,%1,%2,%3}, [%4];" \
                 : "=r"((r)[0]), "=r"((r)[1]), "=r"((r)[2]), "=r"((r)[3])     \
                 : "r"(addr))

// ---------------- MLP GEMM: O = act(A @ W + b), N = DH = 256 ---------------
__global__ __launch_bounds__(NTHREADS, 2)
void mlp_gemm_kernel(const float* __restrict__ in0, const float* __restrict__ in1,
                     const float* __restrict__ Wd0, const float* __restrict__ Wd1,
                     const float* __restrict__ bd0, const float* __restrict__ bd1,
                     int layer)
{
    const int z = blockIdx.z;
    const float* A;
    int K, relu;
    float* Omd;
    __half *Oh, *Ol;
    if (layer == 0) {
        A = z ? in1 : in0;
        Omd = z ? g_hid1 : g_hid0;
        Oh = 0; Ol = 0;
        K = DIN; relu = 1;
    } else {
        A = z ? g_hid1 : g_hid0;
        Omd = z ? g_md1 : g_md0;
        Oh = z ? g_bh : g_ah;
        Ol = z ? g_bl : g_al;
        K = DH; relu = 0;
    }
    const float* W = z ? Wd1 : Wd0;
    const float* bias = z ? bd1 : bd0;

    __shared__ float As[BK][BM];
    __shared__ float Bs[BK][BN];

    const int tid = threadIdx.x;
    const int tx = tid & 15, ty = tid >> 4;
    const int r0 = blockIdx.y * BM;
    const int c0 = blockIdx.x * BN;

    float acc[8][8];
#pragma unroll
    for (int i = 0; i < 8; i++)
#pragma unroll
        for (int j = 0; j < 8; j++) acc[i][j] = 0.0f;

    for (int k0 = 0; k0 < K; k0 += BK) {
#pragma unroll
        for (int i = 0; i < 2; i++) {
            int f = tid * 2 + i;
            int row = f >> 2;
            int kq = (f & 3) << 2;
            float4 v = *(const float4*)(A + (size_t)(r0 + row) * K + k0 + kq);
            As[kq + 0][row] = v.x; As[kq + 1][row] = v.y;
            As[kq + 2][row] = v.z; As[kq + 3][row] = v.w;
        }
#pragma unroll
        for (int i = 0; i < 2; i++) {
            int f = tid * 2 + i;
            int kk = f >> 5;
            int nq = (f & 31) << 2;
            *(float4*)&Bs[kk][nq] =
                *(const float4*)(W + (size_t)(k0 + kk) * DH + c0 + nq);
        }
        __syncthreads();
#pragma unroll
        for (int kk = 0; kk < BK; kk++) {
            float a[8], b[8];
            *(float4*)&a[0] = *(float4*)&As[kk][ty * 8];
            *(float4*)&a[4] = *(float4*)&As[kk][ty * 8 + 4];
            *(float4*)&b[0] = *(float4*)&Bs[kk][tx * 8];
            *(float4*)&b[4] = *(float4*)&Bs[kk][tx * 8 + 4];
#pragma unroll
            for (int i = 0; i < 8; i++)
#pragma unroll
                for (int j = 0; j < 8; j++)
                    acc[i][j] = fmaf(a[i], b[j], acc[i][j]);
        }
        __syncthreads();
    }

    float bv[8];
    *(float4*)&bv[0] = *(const float4*)(bias + c0 + tx * 8);
    *(float4*)&bv[4] = *(const float4*)(bias + c0 + tx * 8 + 4);

#pragma unroll
    for (int i = 0; i < 8; i++) {
        int row = r0 + ty * 8 + i;
        float f[8];
#pragma unroll
        for (int j = 0; j < 8; j++) f[j] = acc[i][j] + bv[j];
        if (relu) {
#pragma unroll
            for (int j = 0; j < 8; j++) f[j] = fmaxf(f[j], 0.0f);
            *(float4*)(Omd + (size_t)row * DH + c0 + tx * 8) = *(float4*)&f[0];
            *(float4*)(Omd + (size_t)row * DH + c0 + tx * 8 + 4) = *(float4*)&f[4];
        } else {
            __half hh[8], ll[8];
#pragma unroll
            for (int j = 0; j < 8; j++) {
                __half h = __float2half_rn(f[j]);
                hh[j] = h;
                ll[j] = __float2half_rn(f[j] - __half2float(h));
            }
            size_t off = (size_t)row * DH + c0 + tx * 8;
            *(float4*)(Omd + off)     = *(float4*)&f[0];
            *(float4*)(Omd + off + 4) = *(float4*)&f[4];
            *(uint4*)(Oh + off) = *(uint4*)hh;
            *(uint4*)(Ol + off) = *(uint4*)ll;
        }
    }
}

// ---------------- no-op (aligns ncu -s 5 capture onto sim kernel) ----------
__global__ void noop_kernel() {}

// ---------------- sim GEMM: fp16 m16n8k16, ldmatrix + frag reuse -----------
__global__ __launch_bounds__(256, 1)
void sim_mma_kernel(float* __restrict__ C)
{
    extern __shared__ __align__(128) __half hsm[];
    __shared__ float wmax[8];

    const int tid = threadIdx.x;
    const int lid = tid & 31, wid = tid >> 5;
    const int warp_m = wid >> 2, warp_n = wid & 3;   // 2 x 4 warps, 64x64 each
    const int gr = lid >> 2, gc = lid & 3;
    const int m0 = blockIdx.y * TM;
    const int n0 = blockIdx.x * TN;

    const uint32_t sbase = (uint32_t)__cvta_generic_to_shared(hsm);

    // cp.async slots (unchanged from R8):
    const int arow = tid & 127;
    const __half* gA = (tid < 128 ? g_ah : g_al) + (size_t)(m0 + arow) * DH;
    const __half* gBh = g_bh + (size_t)(n0 + tid) * DH;
    const __half* gBl = g_bl + (size_t)(n0 + tid) * DH;
    const uint32_t aoff = ((tid < 128 ? AH_OFF : AL_OFF) + arow * SH) * 2;
    const uint32_t bhoff = (BH_OFF + tid * SH) * 2;
    const uint32_t bloff = (BL_OFF + tid * SH) * 2;

    // ldmatrix lane addressing (halves):
    //   A x4 tile: m = lane&15, k-half = (lane>>4)*8
    //   B x4 pair: n = (lane&7) + ((lane>>4)&1)*8, k-half = ((lane>>3)&1)*8
    const uint32_t a_lm = ((warp_m * 64 + (lid & 15)) * SH + (lid >> 4) * 8) * 2;
    const uint32_t b_lm = ((warp_n * 64 + (lid & 7) + ((lid >> 4) & 1) * 8) * SH
                           + ((lid >> 3) & 1) * 8) * 2;

    float acc[4][8][4];
#pragma unroll
    for (int i = 0; i < 4; i++)
#pragma unroll
        for (int j = 0; j < 8; j++)
#pragma unroll
            for (int q = 0; q < 4; q++) acc[i][j][q] = 0.0f;

#define ISSUE(s)                                                               \
    do {                                                                       \
        const int k_ = (s) * KCH;                                              \
        const uint32_t bb_ = sbase + ((s) & (NBUF - 1)) * STG * 2;             \
        cp16(bb_ + aoff,       gA + k_);                                       \
        cp16(bb_ + aoff + 16,  gA + k_ + 8);                                   \
        cp16(bb_ + bhoff,      gBh + k_);                                      \
        cp16(bb_ + bhoff + 16, gBh + k_ + 8);                                  \
        cp16(bb_ + bloff,      gBl + k_);                                      \
        cp16(bb_ + bloff + 16, gBl + k_ + 8);                                  \
        asm volatile("cp.async.commit_group;" ::: "memory");                   \
    } while (0)

#define MMA(d, A4, off, b0, b1)                                               \
    asm volatile(                                                             \
        "mma.sync.aligned.m16n8k16.row.col.f32.f16.f16.f32 "                  \
        "{%0,%1,%2,%3}, {%4,%5,%6,%7}, {%8,%9}, {%0,%1,%2,%3};"               \
        : "+f"((d)[0]), "+f"((d)[1]), "+f"((d)[2]), "+f"((d)[3])              \
        : "r"((A4)[(off)]), "r"((A4)[(off) + 1]),                             \
          "r"((A4)[(off) + 2]), "r"((A4)[(off) + 3]),                         \
          "r"(b0), "r"(b1))

    ISSUE(0); ISSUE(1); ISSUE(2);

#pragma unroll 1
    for (int s = 0; s < NST; s++) {
        if (s <= NST - 3)
            asm volatile("cp.async.wait_group 2;" ::: "memory");
        else if (s == NST - 2)
            asm volatile("cp.async.wait_group 1;" ::: "memory");
        else
            asm volatile("cp.async.wait_group 0;" ::: "memory");
        __syncthreads();
        if (s + 3 < NST) ISSUE(s + 3);

        const uint32_t buf = sbase + (s & (NBUF - 1)) * STG * 2;
        uint32_t Ah[16], Al[16], Bh[16], Bl[16];
#pragma unroll
        for (int i = 0; i < 4; i++) {
            LDSM4(&Ah[4 * i], buf + AH_OFF * 2 + i * 16 * SH * 2 + a_lm);
            LDSM4(&Al[4 * i], buf + AL_OFF * 2 + i * 16 * SH * 2 + a_lm);
        }
#pragma unroll
        for (int j = 0; j < 4; j++) {
            LDSM4(&Bh[4 * j], buf + BH_OFF * 2 + j * 16 * SH * 2 + b_lm);
            LDSM4(&Bl[4 * j], buf + BL_OFF * 2 + j * 16 * SH * 2 + b_lm);
        }
        // B frag for n-tile j: regs B[(j>>1)*4 + (j&1)*2 + {0,1}]
#pragma unroll
        for (int i = 0; i < 4; i++)
#pragma unroll
            for (int j = 0; j < 8; j++) {
                const int bi = (j >> 1) * 4 + (j & 1) * 2;
                MMA(acc[i][j], Ah, 4 * i, Bh[bi], Bh[bi + 1]);   // hh
                MMA(acc[i][j], Al, 4 * i, Bh[bi], Bh[bi + 1]);   // lh
                MMA(acc[i][j], Ah, 4 * i, Bl[bi], Bl[bi + 1]);   // hl
            }
        __syncthreads();
    }
#undef ISSUE

    // ---- epilogue: streaming stores + block max ----
    float bmax = -3.0e38f;
#pragma unroll
    for (int i = 0; i < 4; i++) {
#pragma unroll
        for (int j = 0; j < 8; j++) {
            int row = m0 + warp_m * 64 + i * 16 + gr;
            int col = n0 + warp_n * 64 + j * 8 + gc * 2;
            float* d0 = C + (size_t)row * NCOLS + col;
            float* d1 = d0 + 8 * (size_t)NCOLS;
            asm volatile("st.global.cs.v2.f32 [%0], {%1,%2};"
                         :: "l"(d0), "f"(acc[i][j][0]), "f"(acc[i][j][1]) : "memory");
            asm volatile("st.global.cs.v2.f32 [%0], {%1,%2};"
                         :: "l"(d1), "f"(acc[i][j][2]), "f"(acc[i][j][3]) : "memory");
            bmax = fmaxf(bmax, fmaxf(fmaxf(acc[i][j][0], acc[i][j][1]),
                                     fmaxf(acc[i][j][2], acc[i][j][3])));
        }
    }
#pragma unroll
    for (int o = 16; o; o >>= 1) bmax = fmaxf(bmax, __shfl_xor_sync(~0u, bmax, o));
    if (lid == 0) wmax[wid] = bmax;
    __syncthreads();
    if (tid == 0) {
        float mm = wmax[0];
#pragma unroll
        for (int i = 1; i < 8; i++) mm = fmaxf(mm, wmax[i]);
        g_blockmax[blockIdx.y * gridDim.x + blockIdx.x] = mm;
    }
}

// ---------------- threshold: radix-select over 2048 block maxima -----------
__global__ void thresh_kernel()
{
    __shared__ unsigned int cs[32];
    __shared__ unsigned int Ts;
    const int tid = threadIdx.x;  // 1024 threads
    const int w = tid >> 5, l = tid & 31;
    unsigned int k0 = fkey(g_blockmax[tid]);
    unsigned int k1 = fkey(g_blockmax[tid + 1024]);
    if (tid == 0) Ts = 0u;
    __syncthreads();
    for (int bit = 31; bit >= 8; bit--) {
        unsigned int Tc = Ts | (1u << bit);
        unsigned int c = (unsigned)(k0 >= Tc) + (unsigned)(k1 >= Tc);
#pragma unroll
        for (int o = 16; o; o >>= 1) c += __shfl_xor_sync(~0u, c, o);
        if (l == 0) cs[w] = c;
        __syncthreads();
        if (tid < 32) {
            unsigned int t = cs[tid];
#pragma unroll
            for (int o = 16; o; o >>= 1) t += __shfl_xor_sync(~0u, t, o);
            if (tid == 0 && t >= TOPK) Ts = Tc;
        }
        __syncthreads();
    }
    if (tid == 0) {
        unsigned int T = Ts;
        float f;
        if (T < 0x01000000u) f = -3.0e38f;
        else if (T & 0x80000000u) f = __uint_as_float(T ^ 0x80000000u);
        else f = __uint_as_float(~T);
        g_thresh = f - (fabsf(f) * 1e-4f + 1e-6f);   // fp16-split ordering margin
        g_ccount = 0;
    }
}

// ---------------- collect candidates >= threshold ---------------------------
__device__ __forceinline__ void push_cand(float v, unsigned int idx)
{
    unsigned int pos = atomicAdd(&g_ccount, 1u);
    if (pos < CAND_BUF) {
        unsigned long long e =
            ((unsigned long long)fkey(v) << 32) | (unsigned int)(~idx);
        g_cand[pos] = e;
    }
}

__global__ void collect_kernel(const float* __restrict__ S)
{
    const float T = g_thresh;
    const size_t total4 = (size_t)MROWS * NCOLS / 4;
    const size_t stride = (size_t)gridDim.x * blockDim.x;
    for (size_t q = (size_t)blockIdx.x * blockDim.x + threadIdx.x;
         q < total4; q += stride) {
        float4 v = ((const float4*)S)[q];
        unsigned int base = (unsigned int)(q * 4);
        if (v.x >= T) push_cand(v.x, base + 0);
        if (v.y >= T) push_cand(v.y, base + 1);
        if (v.z >= T) push_cand(v.z, base + 2);
        if (v.w >= T) push_cand(v.w, base + 3);
    }
}

// ---------------- recompute candidate values exactly (fp64, warp/cand) -----
__global__ void recompute_kernel()
{
    unsigned int cnt = g_ccount;
    if (cnt > CAND_BUF) cnt = CAND_BUF;
    const int gw = (blockIdx.x * blockDim.x + threadIdx.x) >> 5;
    const int nw = (gridDim.x * blockDim.x) >> 5;
    const int lid = threadIdx.x & 31;
    for (unsigned int i = gw; i < cnt; i += nw) {
        unsigned long long e = g_cand[i];
        unsigned int idx = ~(unsigned int)(e & 0xFFFFFFFFull);
        int r = idx >> 13, c = idx & (NCOLS - 1);
        const float* ar = g_md0 + (size_t)r * DH;
        const float* br = g_md1 + (size_t)c * DH;
        double s = 0.0;
#pragma unroll
        for (int k = 0; k < 8; k++) {
            int kk = lid + k * 32;
            s = fma((double)ar[kk], (double)br[kk], s);
        }
#pragma unroll
        for (int o = 16; o; o >>= 1) s += __shfl_down_sync(0xffffffffu, s, o);
        if (lid == 0) {
            float v = (float)s;
            g_cand[i] = ((unsigned long long)fkey(v) << 32)
                      | (unsigned long long)(e & 0xFFFFFFFFull);
        }
    }
}

// ---------------- final: sort candidates, emit (row, col) pairs ------------
__global__ void final_kernel(float* __restrict__ out)
{
    __shared__ unsigned long long s[CAND_SORT];
    __shared__ unsigned long long red[32];
    const int tid = threadIdx.x;  // 1024 threads
    unsigned int cnt = g_ccount;
    if (cnt > CAND_BUF) cnt = CAND_BUF;

    if (cnt <= CAND_SORT) {
        for (int i = tid; i < CAND_SORT; i += 1024)
            s[i] = (i < (int)cnt) ? g_cand[i] : 0ull;
        __syncthreads();
        for (int k = 2; k <= CAND_SORT; k <<= 1) {
            for (int j = k >> 1; j > 0; j >>= 1) {
                for (int i = tid; i < CAND_SORT; i += 1024) {
                    int ixj = i ^ j;
                    if (ixj > i) {
                        bool desc = ((i & k) == 0);
                        unsigned long long a = s[i], b = s[ixj];
                        if (desc ? (a < b) : (a > b)) { s[i] = b; s[ixj] = a; }
                    }
                }
                __syncthreads();
            }
        }
        for (int i = tid; i < TOPK; i += 1024) {
            unsigned int idx = ~(unsigned int)(s[i] & 0xFFFFFFFFull);
            out[2 * i + 0] = (float)(idx >> 13);
            out[2 * i + 1] = (float)(idx & (NCOLS - 1));
        }
    } else {
        for (int r = 0; r < TOPK; r++) {
            unsigned long long best = 0ull;
            for (unsigned int i = tid; i < cnt; i += 1024) {
                unsigned long long v = g_cand[i];
                if (v > best) best = v;
            }
#pragma unroll
            for (int o = 16; o; o >>= 1) {
                unsigned long long other = __shfl_down_sync(0xffffffffu, best, o);
                if (other > best) best = other;
            }
            if ((tid & 31) == 0) red[tid >> 5] = best;
            __syncthreads();
            if (tid < 32) {
                unsigned long long b = red[tid];
#pragma unroll
                for (int o = 16; o; o >>= 1) {
                    unsigned long long other = __shfl_down_sync(0xffffffffu, b, o);
                    if (other > b) b = other;
                }
                if (tid == 0) red[0] = b;
            }
            __syncthreads();
            best = red[0];
            for (unsigned int i = tid; i < cnt; i += 1024)
                if (g_cand[i] == best) g_cand[i] = 0ull;
            if (tid == 0) {
                unsigned int idx = ~(unsigned int)(best & 0xFFFFFFFFull);
                out[2 * r + 0] = (float)(idx >> 13);
                out[2 * r + 1] = (float)(idx & (NCOLS - 1));
            }
            __syncthreads();
        }
    }
}

// ---------------- launch ----------------------------------------------------
extern "C" void kernel_launch(void* const* d_in, const int* in_sizes, int n_in,
                              void* d_out, int out_size)
{
    const float* desc0 = (const float*)d_in[0];
    const float* desc1 = (const float*)d_in[1];
    const float* W0a = (const float*)d_in[2];
    const float* b0a = (const float*)d_in[3];
    const float* W0b = (const float*)d_in[4];
    const float* b0b = (const float*)d_in[5];
    const float* W1a = (const float*)d_in[6];
    const float* b1a = (const float*)d_in[7];
    const float* W1b = (const float*)d_in[8];
    const float* b1b = (const float*)d_in[9];

    float* out = (float*)d_out;
    float* sim = out + 2 * TOPK;  // indices first, then sim [8192, 8192]

    cudaFuncSetAttribute(sim_mma_kernel,
                         cudaFuncAttributeMaxDynamicSharedMemorySize, SIM_SMEM);

    dim3 mgrid(DH / BN, MROWS / BM, 2);   // (2, 64, 2)
    mlp_gemm_kernel<<<mgrid, NTHREADS>>>(desc0, desc1, W0a, W1a, b0a, b1a, 0);
    mlp_gemm_kernel<<<mgrid, NTHREADS>>>(desc0, desc1, W0b, W1b, b0b, b1b, 1);

    noop_kernel<<<1, 32>>>();             // ncu -s 5 alignment: sim is launch #4

    dim3 sgrid(NBX, NBY);                 // (32, 64)
    sim_mma_kernel<<<sgrid, 256, SIM_SMEM>>>(sim);

    thresh_kernel<<<1, 1024>>>();
    collect_kernel<<<2048, 256>>>(sim);
    recompute_kernel<<<256, 256>>>();
    final_kernel<<<1, 1024>>>(out);
}

// round 11
// speedup vs baseline: 1.6122x; 1.5985x over previous
#include <cuda_runtime.h>
#include <cuda_fp16.h>
#include <cstdint>

#define MROWS 8192
#define NCOLS 8192
#define DIN   128
#define DH    256
#define TOPK  512

// ---------- MLP tiling ----------
#define BM 128
#define BN 128
#define BK 16
#define NTHREADS 256

// ---------- sim tiling (fp16 m16n8k16, single-term, ldmatrix feed) ----------
#define TM 128
#define TN 256
#define KCH 16               // k per stage
#define NST 16               // 256 / 16 stages
#define NBUF 4
#define SH 24                // halves per smem row (16 data + 8 pad)
#define BH_OFF (128 * SH)    // B rows after 128 A rows
#define STG (384 * SH)       // halves per stage buffer (9216)
#define SIM_SMEM (NBUF * STG * 2)   // 73728 B

#define NBX (NCOLS / TN)     // 32
#define NBY (MROWS / TM)     // 64
#define NBLOCKS (NBX * NBY)  // 2048

#define CAND_BUF  32768
#define CAND_SORT 4096

// ---------------- scratch (device globals; no allocation allowed) ----------
__device__ __align__(128) float g_hid0[MROWS * DH];
__device__ __align__(128) float g_hid1[NCOLS * DH];
__device__ __align__(128) float g_md0[MROWS * DH];    // exact fp32 (recompute)
__device__ __align__(128) float g_md1[NCOLS * DH];
__device__ __align__(128) __half g_ah[MROWS * DH];    // fp16
__device__ __align__(128) __half g_bh[NCOLS * DH];
__device__ float g_blockmax[NBLOCKS];
__device__ float g_thresh;
__device__ unsigned int g_ccount;
__device__ unsigned long long g_cand[CAND_BUF];

// monotone float -> uint key
__device__ __forceinline__ unsigned int fkey(float f) {
    unsigned int u = __float_as_uint(f);
    return (u & 0x80000000u) ? ~u : (u | 0x80000000u);
}

__device__ __forceinline__ void cp16(uint32_t smem_dst, const void* src) {
    asm volatile("cp.async.cg.shared.global [%0], [%1], 16;"
                 :: "r"(smem_dst), "l"(src) : "memory");
}

#define LDSM4(r, addr)                                                        \
    asm volatile("ldmatrix.sync.aligned.m8n8.x4.shared.b16 {%0,%1,%2,%3}, [%4];" \
                 : "=r"((r)[0]), "=r"((r)[1]), "=r"((r)[2]), "=r"((r)[3])     \
                 : "r"(addr))

// ---------------- MLP GEMM: O = act(A @ W + b), N = DH = 256 ---------------
__global__ __launch_bounds__(NTHREADS, 2)
void mlp_gemm_kernel(const float* __restrict__ in0, const float* __restrict__ in1,
                     const float* __restrict__ Wd0, const float* __restrict__ Wd1,
                     const float* __restrict__ bd0, const float* __restrict__ bd1,
                     int layer)
{
    const int z = blockIdx.z;
    const float* A;
    int K, relu;
    float* Omd;
    __half* Oh;
    if (layer == 0) {
        A = z ? in1 : in0;
        Omd = z ? g_hid1 : g_hid0;
        Oh = 0;
        K = DIN; relu = 1;
    } else {
        A = z ? g_hid1 : g_hid0;
        Omd = z ? g_md1 : g_md0;
        Oh = z ? g_bh : g_ah;
        K = DH; relu = 0;
    }
    const float* W = z ? Wd1 : Wd0;
    const float* bias = z ? bd1 : bd0;

    __shared__ float As[BK][BM];
    __shared__ float Bs[BK][BN];

    const int tid = threadIdx.x;
    const int tx = tid & 15, ty = tid >> 4;
    const int r0 = blockIdx.y * BM;
    const int c0 = blockIdx.x * BN;

    float acc[8][8];
#pragma unroll
    for (int i = 0; i < 8; i++)
#pragma unroll
        for (int j = 0; j < 8; j++) acc[i][j] = 0.0f;

    for (int k0 = 0; k0 < K; k0 += BK) {
#pragma unroll
        for (int i = 0; i < 2; i++) {
            int f = tid * 2 + i;
            int row = f >> 2;
            int kq = (f & 3) << 2;
            float4 v = *(const float4*)(A + (size_t)(r0 + row) * K + k0 + kq);
            As[kq + 0][row] = v.x; As[kq + 1][row] = v.y;
            As[kq + 2][row] = v.z; As[kq + 3][row] = v.w;
        }
#pragma unroll
        for (int i = 0; i < 2; i++) {
            int f = tid * 2 + i;
            int kk = f >> 5;
            int nq = (f & 31) << 2;
            *(float4*)&Bs[kk][nq] =
                *(const float4*)(W + (size_t)(k0 + kk) * DH + c0 + nq);
        }
        __syncthreads();
#pragma unroll
        for (int kk = 0; kk < BK; kk++) {
            float a[8], b[8];
            *(float4*)&a[0] = *(float4*)&As[kk][ty * 8];
            *(float4*)&a[4] = *(float4*)&As[kk][ty * 8 + 4];
            *(float4*)&b[0] = *(float4*)&Bs[kk][tx * 8];
            *(float4*)&b[4] = *(float4*)&Bs[kk][tx * 8 + 4];
#pragma unroll
            for (int i = 0; i < 8; i++)
#pragma unroll
                for (int j = 0; j < 8; j++)
                    acc[i][j] = fmaf(a[i], b[j], acc[i][j]);
        }
        __syncthreads();
    }

    float bv[8];
    *(float4*)&bv[0] = *(const float4*)(bias + c0 + tx * 8);
    *(float4*)&bv[4] = *(const float4*)(bias + c0 + tx * 8 + 4);

#pragma unroll
    for (int i = 0; i < 8; i++) {
        int row = r0 + ty * 8 + i;
        float f[8];
#pragma unroll
        for (int j = 0; j < 8; j++) f[j] = acc[i][j] + bv[j];
        if (relu) {
#pragma unroll
            for (int j = 0; j < 8; j++) f[j] = fmaxf(f[j], 0.0f);
            *(float4*)(Omd + (size_t)row * DH + c0 + tx * 8) = *(float4*)&f[0];
            *(float4*)(Omd + (size_t)row * DH + c0 + tx * 8 + 4) = *(float4*)&f[4];
        } else {
            __half hh[8];
#pragma unroll
            for (int j = 0; j < 8; j++) hh[j] = __float2half_rn(f[j]);
            size_t off = (size_t)row * DH + c0 + tx * 8;
            *(float4*)(Omd + off)     = *(float4*)&f[0];
            *(float4*)(Omd + off + 4) = *(float4*)&f[4];
            *(uint4*)(Oh + off) = *(uint4*)hh;
        }
    }
}

// ---------------- no-op (aligns ncu -s 5 capture onto sim kernel) ----------
__global__ void noop_kernel() {}

// ---------------- sim GEMM: fp16 m16n8k16 single-term, ldmatrix ------------
__global__ __launch_bounds__(256, 1)
void sim_mma_kernel(float* __restrict__ C)
{
    extern __shared__ __align__(128) __half hsm[];
    __shared__ float wmax[8];

    const int tid = threadIdx.x;
    const int lid = tid & 31, wid = tid >> 5;
    const int warp_m = wid >> 2, warp_n = wid & 3;   // 2 x 4 warps, 64x64 each
    const int gr = lid >> 2, gc = lid & 3;
    const int m0 = blockIdx.y * TM;
    const int n0 = blockIdx.x * TN;

    const uint32_t sbase = (uint32_t)__cvta_generic_to_shared(hsm);

    // cp.async slots: 3 x 16B per thread per stage
    const int crow = tid >> 1;
    const int chf = (tid & 1) * 8;
    const __half* gA  = g_ah + (size_t)(m0 + crow) * DH + chf;
    const __half* gB0 = g_bh + (size_t)(n0 + crow) * DH + chf;
    const __half* gB1 = g_bh + (size_t)(n0 + 128 + crow) * DH + chf;
    const uint32_t aoff  = (crow * SH + chf) * 2;
    const uint32_t b0off = (BH_OFF + crow * SH + chf) * 2;
    const uint32_t b1off = (BH_OFF + (128 + crow) * SH + chf) * 2;

    // ldmatrix lane addressing (halves)
    const uint32_t a_lm = ((warp_m * 64 + (lid & 15)) * SH + (lid >> 4) * 8) * 2;
    const uint32_t b_lm = ((BH_OFF + (warp_n * 64 + (lid & 7) + ((lid >> 4) & 1) * 8) * SH)
                           + ((lid >> 3) & 1) * 8) * 2;

    float acc[4][8][4];
#pragma unroll
    for (int i = 0; i < 4; i++)
#pragma unroll
        for (int j = 0; j < 8; j++)
#pragma unroll
            for (int q = 0; q < 4; q++) acc[i][j][q] = 0.0f;

#define ISSUE(s)                                                               \
    do {                                                                       \
        const int k_ = (s) * KCH;                                              \
        const uint32_t bb_ = sbase + ((s) & (NBUF - 1)) * STG * 2;             \
        cp16(bb_ + aoff,  gA + k_);                                            \
        cp16(bb_ + b0off, gB0 + k_);                                           \
        cp16(bb_ + b1off, gB1 + k_);                                           \
        asm volatile("cp.async.commit_group;" ::: "memory");                   \
    } while (0)

#define MMA(d, A4, off, b0, b1)                                               \
    asm volatile(                                                             \
        "mma.sync.aligned.m16n8k16.row.col.f32.f16.f16.f32 "                  \
        "{%0,%1,%2,%3}, {%4,%5,%6,%7}, {%8,%9}, {%0,%1,%2,%3};"               \
        : "+f"((d)[0]), "+f"((d)[1]), "+f"((d)[2]), "+f"((d)[3])              \
        : "r"((A4)[(off)]), "r"((A4)[(off) + 1]),                             \
          "r"((A4)[(off) + 2]), "r"((A4)[(off) + 3]),                         \
          "r"(b0), "r"(b1))

    ISSUE(0); ISSUE(1); ISSUE(2);

#pragma unroll 1
    for (int s = 0; s < NST; s++) {
        if (s <= NST - 3)
            asm volatile("cp.async.wait_group 2;" ::: "memory");
        else if (s == NST - 2)
            asm volatile("cp.async.wait_group 1;" ::: "memory");
        else
            asm volatile("cp.async.wait_group 0;" ::: "memory");
        __syncthreads();
        if (s + 3 < NST) ISSUE(s + 3);

        const uint32_t buf = sbase + (s & (NBUF - 1)) * STG * 2;
        uint32_t Ah[16], Bh[16];
#pragma unroll
        for (int i = 0; i < 4; i++)
            LDSM4(&Ah[4 * i], buf + i * 16 * SH * 2 + a_lm);
#pragma unroll
        for (int j = 0; j < 4; j++)
            LDSM4(&Bh[4 * j], buf + j * 16 * SH * 2 + b_lm);
        // B frag for n-tile j: regs Bh[(j>>1)*4 + (j&1)*2 + {0,1}]
#pragma unroll
        for (int i = 0; i < 4; i++)
#pragma unroll
            for (int j = 0; j < 8; j++) {
                const int bi = (j >> 1) * 4 + (j & 1) * 2;
                MMA(acc[i][j], Ah, 4 * i, Bh[bi], Bh[bi + 1]);
            }
        __syncthreads();
    }
#undef ISSUE

    // ---- epilogue: streaming stores + block max ----
    float bmax = -3.0e38f;
#pragma unroll
    for (int i = 0; i < 4; i++) {
#pragma unroll
        for (int j = 0; j < 8; j++) {
            int row = m0 + warp_m * 64 + i * 16 + gr;
            int col = n0 + warp_n * 64 + j * 8 + gc * 2;
            float* d0 = C + (size_t)row * NCOLS + col;
            float* d1 = d0 + 8 * (size_t)NCOLS;
            asm volatile("st.global.cs.v2.f32 [%0], {%1,%2};"
                         :: "l"(d0), "f"(acc[i][j][0]), "f"(acc[i][j][1]) : "memory");
            asm volatile("st.global.cs.v2.f32 [%0], {%1,%2};"
                         :: "l"(d1), "f"(acc[i][j][2]), "f"(acc[i][j][3]) : "memory");
            bmax = fmaxf(bmax, fmaxf(fmaxf(acc[i][j][0], acc[i][j][1]),
                                     fmaxf(acc[i][j][2], acc[i][j][3])));
        }
    }
#pragma unroll
    for (int o = 16; o; o >>= 1) bmax = fmaxf(bmax, __shfl_xor_sync(~0u, bmax, o));
    if (lid == 0) wmax[wid] = bmax;
    __syncthreads();
    if (tid == 0) {
        float mm = wmax[0];
#pragma unroll
        for (int i = 1; i < 8; i++) mm = fmaxf(mm, wmax[i]);
        g_blockmax[blockIdx.y * gridDim.x + blockIdx.x] = mm;
    }
}

// ---------------- threshold: radix-select over 2048 block maxima -----------
__global__ void thresh_kernel()
{
    __shared__ unsigned int cs[32];
    __shared__ unsigned int Ts;
    const int tid = threadIdx.x;  // 1024 threads
    const int w = tid >> 5, l = tid & 31;
    unsigned int k0 = fkey(g_blockmax[tid]);
    unsigned int k1 = fkey(g_blockmax[tid + 1024]);
    if (tid == 0) Ts = 0u;
    __syncthreads();
    for (int bit = 31; bit >= 8; bit--) {
        unsigned int Tc = Ts | (1u << bit);
        unsigned int c = (unsigned)(k0 >= Tc) + (unsigned)(k1 >= Tc);
#pragma unroll
        for (int o = 16; o; o >>= 1) c += __shfl_xor_sync(~0u, c, o);
        if (l == 0) cs[w] = c;
        __syncthreads();
        if (tid < 32) {
            unsigned int t = cs[tid];
#pragma unroll
            for (int o = 16; o; o >>= 1) t += __shfl_xor_sync(~0u, t, o);
            if (tid == 0 && t >= TOPK) Ts = Tc;
        }
        __syncthreads();
    }
    if (tid == 0) {
        unsigned int T = Ts;
        float f;
        if (T < 0x01000000u) f = -3.0e38f;
        else if (T & 0x80000000u) f = __uint_as_float(T ^ 0x80000000u);
        else f = __uint_as_float(~T);
        // wider margin: single-term fp16 GEMM error insurance (~4e-4 rms)
        g_thresh = f - (fabsf(f) * 2e-3f + 1e-5f);
        g_ccount = 0;
    }
}

// ---------------- collect candidates >= threshold ---------------------------
__device__ __forceinline__ void push_cand(float v, unsigned int idx)
{
    unsigned int pos = atomicAdd(&g_ccount, 1u);
    if (pos < CAND_BUF) {
        unsigned long long e =
            ((unsigned long long)fkey(v) << 32) | (unsigned int)(~idx);
        g_cand[pos] = e;
    }
}

__global__ void collect_kernel(const float* __restrict__ S)
{
    const float T = g_thresh;
    const size_t total4 = (size_t)MROWS * NCOLS / 4;
    const size_t stride = (size_t)gridDim.x * blockDim.x;
    for (size_t q = (size_t)blockIdx.x * blockDim.x + threadIdx.x;
         q < total4; q += stride) {
        float4 v = ((const float4*)S)[q];
        unsigned int base = (unsigned int)(q * 4);
        if (v.x >= T) push_cand(v.x, base + 0);
        if (v.y >= T) push_cand(v.y, base + 1);
        if (v.z >= T) push_cand(v.z, base + 2);
        if (v.w >= T) push_cand(v.w, base + 3);
    }
}

// ---------------- recompute candidate values exactly (fp64, warp/cand) -----
__global__ void recompute_kernel()
{
    unsigned int cnt = g_ccount;
    if (cnt > CAND_BUF) cnt = CAND_BUF;
    const int gw = (blockIdx.x * blockDim.x + threadIdx.x) >> 5;
    const int nw = (gridDim.x * blockDim.x) >> 5;
    const int lid = threadIdx.x & 31;
    for (unsigned int i = gw; i < cnt; i += nw) {
        unsigned long long e = g_cand[i];
        unsigned int idx = ~(unsigned int)(e & 0xFFFFFFFFull);
        int r = idx >> 13, c = idx & (NCOLS - 1);
        const float* ar = g_md0 + (size_t)r * DH;
        const float* br = g_md1 + (size_t)c * DH;
        double s = 0.0;
#pragma unroll
        for (int k = 0; k < 8; k++) {
            int kk = lid + k * 32;
            s = fma((double)ar[kk], (double)br[kk], s);
        }
#pragma unroll
        for (int o = 16; o; o >>= 1) s += __shfl_down_sync(0xffffffffu, s, o);
        if (lid == 0) {
            float v = (float)s;
            g_cand[i] = ((unsigned long long)fkey(v) << 32)
                      | (unsigned long long)(e & 0xFFFFFFFFull);
        }
    }
}

// ---------------- final: sort candidates, emit (row, col) pairs ------------
__global__ void final_kernel(float* __restrict__ out)
{
    __shared__ unsigned long long s[CAND_SORT];
    __shared__ unsigned long long red[32];
    const int tid = threadIdx.x;  // 1024 threads
    unsigned int cnt = g_ccount;
    if (cnt > CAND_BUF) cnt = CAND_BUF;

    if (cnt <= CAND_SORT) {
        for (int i = tid; i < CAND_SORT; i += 1024)
            s[i] = (i < (int)cnt) ? g_cand[i] : 0ull;
        __syncthreads();
        for (int k = 2; k <= CAND_SORT; k <<= 1) {
            for (int j = k >> 1; j > 0; j >>= 1) {
                for (int i = tid; i < CAND_SORT; i += 1024) {
                    int ixj = i ^ j;
                    if (ixj > i) {
                        bool desc = ((i & k) == 0);
                        unsigned long long a = s[i], b = s[ixj];
                        if (desc ? (a < b) : (a > b)) { s[i] = b; s[ixj] = a; }
                    }
                }
                __syncthreads();
            }
        }
        for (int i = tid; i < TOPK; i += 1024) {
            unsigned int idx = ~(unsigned int)(s[i] & 0xFFFFFFFFull);
            out[2 * i + 0] = (float)(idx >> 13);
            out[2 * i + 1] = (float)(idx & (NCOLS - 1));
        }
    } else {
        for (int r = 0; r < TOPK; r++) {
            unsigned long long best = 0ull;
            for (unsigned int i = tid; i < cnt; i += 1024) {
                unsigned long long v = g_cand[i];
                if (v > best) best = v;
            }
#pragma unroll
            for (int o = 16; o; o >>= 1) {
                unsigned long long other = __shfl_down_sync(0xffffffffu, best, o);
                if (other > best) best = other;
            }
            if ((tid & 31) == 0) red[tid >> 5] = best;
            __syncthreads();
            if (tid < 32) {
                unsigned long long b = red[tid];
#pragma unroll
                for (int o = 16; o; o >>= 1) {
                    unsigned long long other = __shfl_down_sync(0xffffffffu, b, o);
                    if (other > b) b = other;
                }
                if (tid == 0) red[0] = b;
            }
            __syncthreads();
            best = red[0];
            for (unsigned int i = tid; i < cnt; i += 1024)
                if (g_cand[i] == best) g_cand[i] = 0ull;
            if (tid == 0) {
                unsigned int idx = ~(unsigned int)(best & 0xFFFFFFFFull);
                out[2 * r + 0] = (float)(idx >> 13);
                out[2 * r + 1] = (float)(idx & (NCOLS - 1));
            }
            __syncthreads();
        }
    }
}

// ---------------- launch ----------------------------------------------------
extern "C" void kernel_launch(void* const* d_in, const int* in_sizes, int n_in,
                              void* d_out, int out_size)
{
    const float* desc0 = (const float*)d_in[0];
    const float* desc1 = (const float*)d_in[1];
    const float* W0a = (const float*)d_in[2];
    const float* b0a = (const float*)d_in[3];
    const float* W0b = (const float*)d_in[4];
    const float* b0b = (const float*)d_in[5];
    const float* W1a = (const float*)d_in[6];
    const float* b1a = (const float*)d_in[7];
    const float* W1b = (const float*)d_in[8];
    const float* b1b = (const float*)d_in[9];

    float* out = (float*)d_out;
    float* sim = out + 2 * TOPK;  // indices first, then sim [8192, 8192]

    cudaFuncSetAttribute(sim_mma_kernel,
                         cudaFuncAttributeMaxDynamicSharedMemorySize, SIM_SMEM);

    dim3 mgrid(DH / BN, MROWS / BM, 2);   // (2, 64, 2)
    mlp_gemm_kernel<<<mgrid, NTHREADS>>>(desc0, desc1, W0a, W1a, b0a, b1a, 0);
    mlp_gemm_kernel<<<mgrid, NTHREADS>>>(desc0, desc1, W0b, W1b, b0b, b1b, 1);

    noop_kernel<<<1, 32>>>();             // ncu -s 5 alignment: sim is launch #4

    dim3 sgrid(NBX, NBY);                 // (32, 64)
    sim_mma_kernel<<<sgrid, 256, SIM_SMEM>>>(sim);

    thresh_kernel<<<1, 1024>>>();
    collect_kernel<<<2048, 256>>>(sim);
    recompute_kernel<<<256, 256>>>();
    final_kernel<<<1, 1024>>>(out);
}